// round 4
// baseline (speedup 1.0000x reference)
#include <cuda_runtime.h>
#include <cstdint>
#include <cstddef>

#define BATCH 64
#define SEQT  512
#define DIN   256
#define HDIM  1024
#define DOUT  128
#define GRID  128

typedef unsigned long long u64;

// ---------------- scratch (device globals: allocation-free) ----------------
__device__ __align__(16) static float g_P[(size_t)BATCH * SEQT * HDIM]; // pre-activations
__device__ __align__(16) static float g_S[(size_t)BATCH * SEQT * HDIM]; // layer outputs / h
__device__ volatile unsigned g_flags[GRID];                             // barrier flags (zero-init)

// ---------------- packed f32x2 helpers ----------------
__device__ __forceinline__ void fma2(u64 &d, u64 a, u64 b) {
    asm("fma.rn.f32x2 %0, %1, %2, %0;" : "+l"(d) : "l"(a), "l"(b));
}
__device__ __forceinline__ u64 add2(u64 a, u64 b) {
    u64 r; asm("add.rn.f32x2 %0, %1, %2;" : "=l"(r) : "l"(a), "l"(b)); return r;
}
__device__ __forceinline__ float2 up2(u64 v) {
    float2 f; asm("mov.b64 {%0, %1}, %2;" : "=f"(f.x), "=f"(f.y) : "l"(v)); return f;
}

__device__ __forceinline__ uint32_t smem_u32(const void* p) {
    uint32_t a;
    asm("{ .reg .u64 t; cvta.to.shared.u64 t, %1; cvt.u32.u64 %0, t; }" : "=r"(a) : "l"(p));
    return a;
}
__device__ __forceinline__ void cpasync16(uint32_t dst, const void* src) {
    asm volatile("cp.async.cg.shared.global [%0], [%1], 16;" :: "r"(dst), "l"(src));
}
__device__ __forceinline__ void cpasync_commit() {
    asm volatile("cp.async.commit_group;");
}
__device__ __forceinline__ void cpasync_wait0() {
    asm volatile("cp.async.wait_group 0;" ::: "memory");
}

// ---------------- grid barrier (flag array, no atomics) ----------------
__device__ __forceinline__ void gsync(unsigned gen) {
    __syncthreads();
    if (threadIdx.x == 0) {
        __threadfence();                 // release prior global writes
        g_flags[blockIdx.x] = gen;       // volatile store
    }
    if (threadIdx.x < GRID) {
        while (g_flags[threadIdx.x] < gen) { }
    }
    __syncthreads();
}

// ============================================================================
// Projection GEMM: C[32768][1024] = A[32768][K] @ W[1024][K]^T + (bi + bh)
// ============================================================================
__global__ void __launch_bounds__(256, 2) proj_kernel(
    const float* __restrict__ A, const float* __restrict__ W,
    const float* __restrict__ bi, const float* __restrict__ bh,
    float* __restrict__ C, int K)
{
    __shared__ __align__(16) float sA[16 * 132];
    __shared__ __align__(16) float sB[16 * 132];

    const int tid = threadIdx.x;
    const int tm = blockIdx.x >> 3;
    const int tn = blockIdx.x & 7;
    const int ty = tid >> 4;
    const int tx = tid & 15;
    const int lr = tid >> 2;
    const int lq = tid & 3;

    u64 acc[8][4];
    #pragma unroll
    for (int i = 0; i < 8; i++)
        #pragma unroll
        for (int j = 0; j < 4; j++) acc[i][j] = 0ull;

    const float* Ab = A + (size_t)(tm * 128) * K;
    const float* Wb = W + (size_t)(tn * 128) * K;

    for (int kc = 0; kc < K; kc += 16) {
        __syncthreads();
        #pragma unroll
        for (int p = 0; p < 2; p++) {
            const int rr = lr + p * 64;
            const float4 a4 = __ldg((const float4*)(Ab + (size_t)rr * K + kc + lq * 4));
            const float4 w4 = __ldg((const float4*)(Wb + (size_t)rr * K + kc + lq * 4));
            sA[(lq * 4 + 0) * 132 + rr] = a4.x;
            sA[(lq * 4 + 1) * 132 + rr] = a4.y;
            sA[(lq * 4 + 2) * 132 + rr] = a4.z;
            sA[(lq * 4 + 3) * 132 + rr] = a4.w;
            sB[(lq * 4 + 0) * 132 + rr] = w4.x;
            sB[(lq * 4 + 1) * 132 + rr] = w4.y;
            sB[(lq * 4 + 2) * 132 + rr] = w4.z;
            sB[(lq * 4 + 3) * 132 + rr] = w4.w;
        }
        __syncthreads();
        #pragma unroll
        for (int kk = 0; kk < 16; kk++) {
            const float4 a0 = *(const float4*)&sA[kk * 132 + ty * 4];
            const float4 a1 = *(const float4*)&sA[kk * 132 + 64 + ty * 4];
            const ulonglong2 bq0 = *(const ulonglong2*)&sB[kk * 132 + tx * 4];
            const ulonglong2 bq1 = *(const ulonglong2*)&sB[kk * 132 + 64 + tx * 4];
            const float am[8] = {a0.x, a0.y, a0.z, a0.w, a1.x, a1.y, a1.z, a1.w};
            #pragma unroll
            for (int i = 0; i < 8; i++) {
                u64 ad;
                asm("mov.b64 %0, {%1, %1};" : "=l"(ad) : "f"(am[i]));
                fma2(acc[i][0], ad, bq0.x);
                fma2(acc[i][1], ad, bq0.y);
                fma2(acc[i][2], ad, bq1.x);
                fma2(acc[i][3], ad, bq1.y);
            }
        }
    }

    const int n0 = tn * 128 + tx * 4;
    const int n1 = n0 + 64;
    float4 bia0, bia1;
    {
        const float4 i0 = __ldg((const float4*)(bi + n0));
        const float4 h0 = __ldg((const float4*)(bh + n0));
        const float4 i1 = __ldg((const float4*)(bi + n1));
        const float4 h1 = __ldg((const float4*)(bh + n1));
        bia0 = make_float4(i0.x + h0.x, i0.y + h0.y, i0.z + h0.z, i0.w + h0.w);
        bia1 = make_float4(i1.x + h1.x, i1.y + h1.y, i1.z + h1.z, i1.w + h1.w);
    }
    #pragma unroll
    for (int i = 0; i < 8; i++) {
        const int m = tm * 128 + (i < 4 ? ty * 4 + i : 64 + ty * 4 + (i - 4));
        const float2 c0 = up2(acc[i][0]), c1 = up2(acc[i][1]);
        const float2 c2 = up2(acc[i][2]), c3 = up2(acc[i][3]);
        *(float4*)(C + (size_t)m * HDIM + n0) =
            make_float4(c0.x + bia0.x, c0.y + bia0.y, c1.x + bia0.z, c1.y + bia0.w);
        *(float4*)(C + (size_t)m * HDIM + n1) =
            make_float4(c2.x + bia1.x, c2.y + bia1.y, c3.x + bia1.z, c3.y + bia1.w);
    }
}

// ============================================================================
// Recurrent scan: S[:,t,:] = relu(P[:,t,:] + S[:,t-1,:] @ Whh^T)
// 128 CTAs x 256 thr, 1 CTA/SM, CTA tile [16b x 32o].
// Thread tile 4b x 8o (o interleaved: o = o_t + 4*jj), 16 k-slices x 64k.
// Per-warp self-staging of its own 128-k h range (cp.async + syncwarp only).
// Two-phase smem reduce keeps red at 8x512 u64 (32KB).
// ============================================================================
#define SM_W   0                          // wS[32][1028]
#define SM_H   (32 * 1028)                // hS[16][1028]
#define SM_R   (SM_H + 16 * 1028)         // red: u64[8][512]
#define SCAN_SMEM_BYTES ((SM_R + 8 * 512 * 2) * 4)   // 230,144 B

__global__ void __launch_bounds__(256, 1) scan_kernel(
    const float* __restrict__ P, float* __restrict__ S,
    const float* __restrict__ Whh)
{
    extern __shared__ __align__(16) float sm[];
    float* wS = sm + SM_W;
    float* hS = sm + SM_H;
    u64*   red = (u64*)(sm + SM_R);

    const int tid = threadIdx.x;
    const int cta = blockIdx.x;
    const int b0 = (cta >> 5) * 16;     // batch block
    const int o0 = (cta & 31) * 32;     // output block
    const int ks  = tid >> 4;           // k-slice 0..15 (64 k each)
    const int pos = tid & 15;
    const int b_t = pos & 3;            // b = i*4 + b_t
    const int o_t = pos >> 2;           // o = o_t + 4*jj  (interleaved)
    const int kb  = ks * 64;
    const int warp = tid >> 5;          // stages k range [warp*128, +128)
    const int lane = tid & 31;

    // Load Whh slice (k-major): wS[j][k] = Whh[o0+j][k]
    for (int i = tid; i < 8192; i += 256) {
        const int j = i >> 8, q = i & 255;
        const float4 w4 = __ldg((const float4*)(Whh + (size_t)(o0 + j) * HDIM + q * 4));
        *(float4*)&wS[j * 1028 + q * 4] = w4;
    }

    unsigned gen = g_flags[cta];        // persists across launches

    // Epilogue mapping: 2 adjacent outputs per thread
    const int pb = tid >> 4;
    const int po = (tid & 15) * 2;
    const size_t prow = ((size_t)(b0 + pb) * SEQT) * HDIM + o0 + po;

    // t = 0
    {
        const float2 p2 = *(const float2*)(P + prow);
        *(float2*)(S + prow) = make_float2(fmaxf(p2.x, 0.f), fmaxf(p2.y, 0.f));
    }
    gen++; gsync(gen);

    const uint32_t hS_a = smem_u32(hS);
    const float* Sb = S + (size_t)b0 * SEQT * HDIM;

    // staging geometry: warp covers float4 cols [warp*32, warp*32+32) of all 16 rows
    const int srow  = lane & 15;
    const int scol0 = warp * 32 + (lane >> 4) * 16;   // float4 index

    for (int t = 1; t < SEQT; t++) {
        const float2 p2 = __ldg((const float2*)(P + prow + (size_t)t * HDIM));

        // per-warp staging of own 128-k range of h_{t-1}
        {
            const float* srcrow = Sb + (size_t)srow * SEQT * HDIM + (size_t)(t - 1) * HDIM;
            const uint32_t dstrow = hS_a + (uint32_t)(srow * 1028) * 4;
            #pragma unroll
            for (int c = 0; c < 16; c++) {
                cpasync16(dstrow + (uint32_t)((scol0 + c) * 16),
                          srcrow + (scol0 + c) * 4);
            }
            cpasync_commit();
            cpasync_wait0();
            __syncwarp();
        }

        // compute: 4b x 8o x 64k, k-packed f32x2
        u64 acc[4][8];
        #pragma unroll
        for (int i = 0; i < 4; i++)
            #pragma unroll
            for (int j = 0; j < 8; j++) acc[i][j] = 0ull;

        #pragma unroll 4
        for (int kq = 0; kq < 64; kq += 4) {
            float4 hv[4];
            #pragma unroll
            for (int i = 0; i < 4; i++)
                hv[i] = *(const float4*)&hS[(i * 4 + b_t) * 1028 + kb + kq];
            float4 wv[8];
            #pragma unroll
            for (int j = 0; j < 8; j++)
                wv[j] = *(const float4*)&wS[(o_t + 4 * j) * 1028 + kb + kq];
            #pragma unroll
            for (int i = 0; i < 4; i++)
                #pragma unroll
                for (int j = 0; j < 8; j++) {
                    fma2(acc[i][j], ((const u64*)&hv[i])[0], ((const u64*)&wv[j])[0]);
                    fma2(acc[i][j], ((const u64*)&hv[i])[1], ((const u64*)&wv[j])[1]);
                }
        }

        // two-phase reduce: slices 8..15 write, then 0..7 accumulate
        if (ks >= 8) {
            u64* rr = &red[(ks - 8) * 512];
            #pragma unroll
            for (int i = 0; i < 4; i++)
                #pragma unroll
                for (int j = 0; j < 8; j++)
                    rr[(i * 4 + b_t) * 32 + (o_t + 4 * j)] = acc[i][j];
        }
        __syncthreads();
        if (ks < 8) {
            u64* rr = &red[ks * 512];
            #pragma unroll
            for (int i = 0; i < 4; i++)
                #pragma unroll
                for (int j = 0; j < 8; j++) {
                    const int idx = (i * 4 + b_t) * 32 + (o_t + 4 * j);
                    rr[idx] = add2(rr[idx], acc[i][j]);
                }
        }
        __syncthreads();

        // final reduce over 8 buffers, fold (even,odd) k halves, relu, store
        {
            ulonglong2 v = *(const ulonglong2*)&red[pb * 32 + po];
            u64 s0 = v.x, s1 = v.y;
            #pragma unroll
            for (int w8 = 1; w8 < 8; w8++) {
                const ulonglong2 r = *(const ulonglong2*)&red[w8 * 512 + pb * 32 + po];
                s0 = add2(s0, r.x);
                s1 = add2(s1, r.y);
            }
            const float2 a0 = up2(s0), a1 = up2(s1);
            *(float2*)(S + prow + (size_t)t * HDIM) =
                make_float2(fmaxf(a0.x + a0.y + p2.x, 0.f),
                            fmaxf(a1.x + a1.y + p2.y, 0.f));
        }
        gen++; gsync(gen);
    }
}

// ============================================================================
// FC: out[64][128] = S[:, T-1, :] @ fc_w^T + fc_b
// ============================================================================
__global__ void __launch_bounds__(128) fc_kernel(
    const float* __restrict__ S, const float* __restrict__ fw,
    const float* __restrict__ fb, float* __restrict__ out)
{
    __shared__ __align__(16) float sx[HDIM];
    const int b = blockIdx.x, tid = threadIdx.x;
    const float* xrow = S + ((size_t)b * SEQT + (SEQT - 1)) * HDIM;
    for (int i = tid; i < HDIM / 4; i += 128)
        *(float4*)&sx[i * 4] = __ldcg((const float4*)(xrow + i * 4));
    __syncthreads();
    float acc = 0.f;
    const float* wrow = fw + (size_t)tid * HDIM;
    #pragma unroll 8
    for (int q = 0; q < HDIM / 4; q++) {
        const float4 w4 = __ldg((const float4*)(wrow + q * 4));
        const float4 x4 = *(const float4*)&sx[q * 4];
        acc += w4.x * x4.x + w4.y * x4.y + w4.z * x4.z + w4.w * x4.w;
    }
    out[(size_t)b * DOUT + tid] = acc + __ldg(fb + tid);
}

// ============================================================================
extern "C" void kernel_launch(void* const* d_in, const int* in_sizes, int n_in,
                              void* d_out, int out_size)
{
    const float* x    = (const float*)d_in[0];   // [64,512,256]
    const float* wih0 = (const float*)d_in[1];   // [1024,256]
    const float* wihr = (const float*)d_in[2];   // [2,1024,1024]
    const float* whh  = (const float*)d_in[3];   // [3,1024,1024]
    const float* bih  = (const float*)d_in[4];   // [3,1024]
    const float* bhh  = (const float*)d_in[5];   // [3,1024]
    const float* fcw  = (const float*)d_in[6];   // [128,1024]
    const float* fcb  = (const float*)d_in[7];   // [128]
    float* out = (float*)d_out;                  // [64,128]

    cudaFuncSetAttribute(scan_kernel, cudaFuncAttributeMaxDynamicSharedMemorySize,
                         SCAN_SMEM_BYTES);

    void *pP = nullptr, *pS = nullptr;
    cudaGetSymbolAddress(&pP, g_P);
    cudaGetSymbolAddress(&pS, g_S);
    float* P  = (float*)pP;
    float* Sq = (float*)pS;

    proj_kernel<<<2048, 256>>>(x, wih0, bih, bhh, P, DIN);
    scan_kernel<<<GRID, 256, SCAN_SMEM_BYTES>>>(P, Sq, whh);
    proj_kernel<<<2048, 256>>>(Sq, wihr, bih + HDIM, bhh + HDIM, P, HDIM);
    scan_kernel<<<GRID, 256, SCAN_SMEM_BYTES>>>(P, Sq, whh + (size_t)HDIM * HDIM);
    proj_kernel<<<2048, 256>>>(Sq, wihr + (size_t)HDIM * HDIM, bih + 2 * HDIM, bhh + 2 * HDIM, P, HDIM);
    scan_kernel<<<GRID, 256, SCAN_SMEM_BYTES>>>(P, Sq, whh + 2 * (size_t)HDIM * HDIM);
    fc_kernel<<<BATCH, 128>>>(Sq, fcw, fcb, out);
}

// round 5
// speedup vs baseline: 1.0972x; 1.0972x over previous
#include <cuda_runtime.h>
#include <cstdint>
#include <cstddef>

#define BATCH 64
#define SEQT  512
#define DIN   256
#define HDIM  1024
#define DOUT  128
#define GRID  128

typedef unsigned long long u64;

// ---------------- scratch (device globals: allocation-free) ----------------
__device__ __align__(16) static float g_P[(size_t)BATCH * SEQT * HDIM]; // pre-activations
__device__ __align__(16) static float g_S[(size_t)BATCH * SEQT * HDIM]; // layer outputs / h
__device__ volatile unsigned g_flags[GRID];                             // barrier flags (zero-init)

// ---------------- packed f32x2 helpers ----------------
__device__ __forceinline__ void fma2(u64 &d, u64 a, u64 b) {
    asm("fma.rn.f32x2 %0, %1, %2, %0;" : "+l"(d) : "l"(a), "l"(b));
}
__device__ __forceinline__ u64 add2(u64 a, u64 b) {
    u64 r; asm("add.rn.f32x2 %0, %1, %2;" : "=l"(r) : "l"(a), "l"(b)); return r;
}
__device__ __forceinline__ float2 up2(u64 v) {
    float2 f; asm("mov.b64 {%0, %1}, %2;" : "=f"(f.x), "=f"(f.y) : "l"(v)); return f;
}

__device__ __forceinline__ uint32_t smem_u32(const void* p) {
    uint32_t a;
    asm("{ .reg .u64 t; cvta.to.shared.u64 t, %1; cvt.u32.u64 %0, t; }" : "=r"(a) : "l"(p));
    return a;
}
__device__ __forceinline__ void cpasync16(uint32_t dst, const void* src) {
    asm volatile("cp.async.cg.shared.global [%0], [%1], 16;" :: "r"(dst), "l"(src));
}
__device__ __forceinline__ void cpasync_commit_wait() {
    asm volatile("cp.async.commit_group;");
    asm volatile("cp.async.wait_group 0;" ::: "memory");
}

// ---------------- group barrier: 4 independent groups of 32 CTAs ----------------
// CTA c belongs to group (c>>5); data (h rows, P rows) is exchanged ONLY among
// the 32 CTAs of one batch group, so the barrier is group-local.
__device__ __forceinline__ void gsync(unsigned gen, int gbase) {
    __syncthreads();
    if (threadIdx.x == 0) {
        __threadfence();                 // release prior global writes
        g_flags[blockIdx.x] = gen;       // volatile store
    }
    if (threadIdx.x < 32) {
        while (g_flags[gbase + threadIdx.x] < gen) { }
    }
    __syncthreads();
}

// ============================================================================
// Projection GEMM: C[32768][1024] = A[32768][K] @ W[1024][K]^T + (bi + bh)
// ============================================================================
__global__ void __launch_bounds__(256, 2) proj_kernel(
    const float* __restrict__ A, const float* __restrict__ W,
    const float* __restrict__ bi, const float* __restrict__ bh,
    float* __restrict__ C, int K)
{
    __shared__ __align__(16) float sA[16 * 132];
    __shared__ __align__(16) float sB[16 * 132];

    const int tid = threadIdx.x;
    const int tm = blockIdx.x >> 3;
    const int tn = blockIdx.x & 7;
    const int ty = tid >> 4;
    const int tx = tid & 15;
    const int lr = tid >> 2;
    const int lq = tid & 3;

    u64 acc[8][4];
    #pragma unroll
    for (int i = 0; i < 8; i++)
        #pragma unroll
        for (int j = 0; j < 4; j++) acc[i][j] = 0ull;

    const float* Ab = A + (size_t)(tm * 128) * K;
    const float* Wb = W + (size_t)(tn * 128) * K;

    for (int kc = 0; kc < K; kc += 16) {
        __syncthreads();
        #pragma unroll
        for (int p = 0; p < 2; p++) {
            const int rr = lr + p * 64;
            const float4 a4 = __ldg((const float4*)(Ab + (size_t)rr * K + kc + lq * 4));
            const float4 w4 = __ldg((const float4*)(Wb + (size_t)rr * K + kc + lq * 4));
            sA[(lq * 4 + 0) * 132 + rr] = a4.x;
            sA[(lq * 4 + 1) * 132 + rr] = a4.y;
            sA[(lq * 4 + 2) * 132 + rr] = a4.z;
            sA[(lq * 4 + 3) * 132 + rr] = a4.w;
            sB[(lq * 4 + 0) * 132 + rr] = w4.x;
            sB[(lq * 4 + 1) * 132 + rr] = w4.y;
            sB[(lq * 4 + 2) * 132 + rr] = w4.z;
            sB[(lq * 4 + 3) * 132 + rr] = w4.w;
        }
        __syncthreads();
        #pragma unroll
        for (int kk = 0; kk < 16; kk++) {
            const float4 a0 = *(const float4*)&sA[kk * 132 + ty * 4];
            const float4 a1 = *(const float4*)&sA[kk * 132 + 64 + ty * 4];
            const ulonglong2 bq0 = *(const ulonglong2*)&sB[kk * 132 + tx * 4];
            const ulonglong2 bq1 = *(const ulonglong2*)&sB[kk * 132 + 64 + tx * 4];
            const float am[8] = {a0.x, a0.y, a0.z, a0.w, a1.x, a1.y, a1.z, a1.w};
            #pragma unroll
            for (int i = 0; i < 8; i++) {
                u64 ad;
                asm("mov.b64 %0, {%1, %1};" : "=l"(ad) : "f"(am[i]));
                fma2(acc[i][0], ad, bq0.x);
                fma2(acc[i][1], ad, bq0.y);
                fma2(acc[i][2], ad, bq1.x);
                fma2(acc[i][3], ad, bq1.y);
            }
        }
    }

    const int n0 = tn * 128 + tx * 4;
    const int n1 = n0 + 64;
    float4 bia0, bia1;
    {
        const float4 i0 = __ldg((const float4*)(bi + n0));
        const float4 h0 = __ldg((const float4*)(bh + n0));
        const float4 i1 = __ldg((const float4*)(bi + n1));
        const float4 h1 = __ldg((const float4*)(bh + n1));
        bia0 = make_float4(i0.x + h0.x, i0.y + h0.y, i0.z + h0.z, i0.w + h0.w);
        bia1 = make_float4(i1.x + h1.x, i1.y + h1.y, i1.z + h1.z, i1.w + h1.w);
    }
    #pragma unroll
    for (int i = 0; i < 8; i++) {
        const int m = tm * 128 + (i < 4 ? ty * 4 + i : 64 + ty * 4 + (i - 4));
        const float2 c0 = up2(acc[i][0]), c1 = up2(acc[i][1]);
        const float2 c2 = up2(acc[i][2]), c3 = up2(acc[i][3]);
        *(float4*)(C + (size_t)m * HDIM + n0) =
            make_float4(c0.x + bia0.x, c0.y + bia0.y, c1.x + bia0.z, c1.y + bia0.w);
        *(float4*)(C + (size_t)m * HDIM + n1) =
            make_float4(c2.x + bia1.x, c2.y + bia1.y, c3.x + bia1.z, c3.y + bia1.w);
    }
}

// ============================================================================
// Recurrent scan: S[:,t,:] = relu(P[:,t,:] + S[:,t-1,:] @ Whh^T)
// 128 CTAs x 256 thr, 1 CTA/SM, CTA tile [16b x 32o].
// Thread tile 4b x 8o (o interleaved), 16 k-slices x 64k.
// CTA-wide cp.async staging + syncthreads (R2-proven). Two-phase smem reduce.
// Group-local barrier across the 32 CTAs of each batch block.
// ============================================================================
#define SM_W   0                          // wS[32][1028]
#define SM_H   (32 * 1028)                // hS[16][1028]
#define SM_R   (SM_H + 16 * 1028)         // red: u64[8][512]
#define SCAN_SMEM_BYTES ((SM_R + 8 * 512 * 2) * 4)   // 230,144 B

__global__ void __launch_bounds__(256, 1) scan_kernel(
    const float* __restrict__ P, float* __restrict__ S,
    const float* __restrict__ Whh)
{
    extern __shared__ __align__(16) float sm[];
    float* wS = sm + SM_W;
    float* hS = sm + SM_H;
    u64*   red = (u64*)(sm + SM_R);

    const int tid = threadIdx.x;
    const int cta = blockIdx.x;
    const int gbase = cta & ~31;        // barrier group base (batch group)
    const int b0 = (cta >> 5) * 16;     // batch block
    const int o0 = (cta & 31) * 32;     // output block
    const int ks  = tid >> 4;           // k-slice 0..15 (64 k each)
    const int pos = tid & 15;
    const int b_t = pos & 3;            // b = i*4 + b_t
    const int o_t = pos >> 2;           // o = o_t + 4*jj (interleaved)
    const int kb  = ks * 64;

    // Load Whh slice (k-major): wS[j][k] = Whh[o0+j][k]
    for (int i = tid; i < 8192; i += 256) {
        const int j = i >> 8, q = i & 255;
        const float4 w4 = __ldg((const float4*)(Whh + (size_t)(o0 + j) * HDIM + q * 4));
        *(float4*)&wS[j * 1028 + q * 4] = w4;
    }

    unsigned gen = g_flags[cta];        // persists across launches

    // Epilogue mapping: 2 adjacent outputs per thread
    const int pb = tid >> 4;
    const int po = (tid & 15) * 2;
    const size_t prow = ((size_t)(b0 + pb) * SEQT) * HDIM + o0 + po;

    // t = 0
    {
        const float2 p2 = *(const float2*)(P + prow);
        *(float2*)(S + prow) = make_float2(fmaxf(p2.x, 0.f), fmaxf(p2.y, 0.f));
    }
    gen++; gsync(gen, gbase);

    const uint32_t hS_a = smem_u32(hS);
    const float* Sb = S + (size_t)b0 * SEQT * HDIM;

    for (int t = 1; t < SEQT; t++) {
        const float2 p2 = __ldg((const float2*)(P + prow + (size_t)t * HDIM));

        // CTA-wide staging of h_{t-1}[b0..b0+16) (cp.async .cg = L2-coherent)
        {
            const size_t tprev = (size_t)(t - 1) * HDIM;
            #pragma unroll
            for (int p = 0; p < 16; p++) {
                const int i = p * 256 + tid;
                const int bb = i >> 8, qq = i & 255;
                cpasync16(hS_a + (uint32_t)(bb * 1028 + qq * 4) * 4,
                          Sb + (size_t)bb * SEQT * HDIM + tprev + qq * 4);
            }
            cpasync_commit_wait();
        }
        __syncthreads();

        // compute: 4b x 8o x 64k, k-packed f32x2
        u64 acc[4][8];
        #pragma unroll
        for (int i = 0; i < 4; i++)
            #pragma unroll
            for (int j = 0; j < 8; j++) acc[i][j] = 0ull;

        #pragma unroll 2
        for (int kq = 0; kq < 64; kq += 4) {
            float4 hv[4];
            #pragma unroll
            for (int i = 0; i < 4; i++)
                hv[i] = *(const float4*)&hS[(i * 4 + b_t) * 1028 + kb + kq];
            float4 wv[8];
            #pragma unroll
            for (int j = 0; j < 8; j++)
                wv[j] = *(const float4*)&wS[(o_t + 4 * j) * 1028 + kb + kq];
            #pragma unroll
            for (int i = 0; i < 4; i++)
                #pragma unroll
                for (int j = 0; j < 8; j++) {
                    fma2(acc[i][j], ((const u64*)&hv[i])[0], ((const u64*)&wv[j])[0]);
                    fma2(acc[i][j], ((const u64*)&hv[i])[1], ((const u64*)&wv[j])[1]);
                }
        }

        // two-phase reduce: slices 8..15 write, then 0..7 accumulate
        if (ks >= 8) {
            u64* rr = &red[(ks - 8) * 512];
            #pragma unroll
            for (int i = 0; i < 4; i++)
                #pragma unroll
                for (int j = 0; j < 8; j++)
                    rr[(i * 4 + b_t) * 32 + (o_t + 4 * j)] = acc[i][j];
        }
        __syncthreads();
        if (ks < 8) {
            u64* rr = &red[ks * 512];
            #pragma unroll
            for (int i = 0; i < 4; i++)
                #pragma unroll
                for (int j = 0; j < 8; j++) {
                    const int idx = (i * 4 + b_t) * 32 + (o_t + 4 * j);
                    rr[idx] = add2(rr[idx], acc[i][j]);
                }
        }
        __syncthreads();

        // final reduce over 8 buffers, fold (even,odd) k halves, relu, store
        {
            ulonglong2 v = *(const ulonglong2*)&red[pb * 32 + po];
            u64 s0 = v.x, s1 = v.y;
            #pragma unroll
            for (int w8 = 1; w8 < 8; w8++) {
                const ulonglong2 r = *(const ulonglong2*)&red[w8 * 512 + pb * 32 + po];
                s0 = add2(s0, r.x);
                s1 = add2(s1, r.y);
            }
            const float2 a0 = up2(s0), a1 = up2(s1);
            *(float2*)(S + prow + (size_t)t * HDIM) =
                make_float2(fmaxf(a0.x + a0.y + p2.x, 0.f),
                            fmaxf(a1.x + a1.y + p2.y, 0.f));
        }
        gen++; gsync(gen, gbase);
    }
}

// ============================================================================
// FC: out[64][128] = S[:, T-1, :] @ fc_w^T + fc_b
// ============================================================================
__global__ void __launch_bounds__(128) fc_kernel(
    const float* __restrict__ S, const float* __restrict__ fw,
    const float* __restrict__ fb, float* __restrict__ out)
{
    __shared__ __align__(16) float sx[HDIM];
    const int b = blockIdx.x, tid = threadIdx.x;
    const float* xrow = S + ((size_t)b * SEQT + (SEQT - 1)) * HDIM;
    for (int i = tid; i < HDIM / 4; i += 128)
        *(float4*)&sx[i * 4] = __ldcg((const float4*)(xrow + i * 4));
    __syncthreads();
    float acc = 0.f;
    const float* wrow = fw + (size_t)tid * HDIM;
    #pragma unroll 8
    for (int q = 0; q < HDIM / 4; q++) {
        const float4 w4 = __ldg((const float4*)(wrow + q * 4));
        const float4 x4 = *(const float4*)&sx[q * 4];
        acc += w4.x * x4.x + w4.y * x4.y + w4.z * x4.z + w4.w * x4.w;
    }
    out[(size_t)b * DOUT + tid] = acc + __ldg(fb + tid);
}

// ============================================================================
extern "C" void kernel_launch(void* const* d_in, const int* in_sizes, int n_in,
                              void* d_out, int out_size)
{
    const float* x    = (const float*)d_in[0];   // [64,512,256]
    const float* wih0 = (const float*)d_in[1];   // [1024,256]
    const float* wihr = (const float*)d_in[2];   // [2,1024,1024]
    const float* whh  = (const float*)d_in[3];   // [3,1024,1024]
    const float* bih  = (const float*)d_in[4];   // [3,1024]
    const float* bhh  = (const float*)d_in[5];   // [3,1024]
    const float* fcw  = (const float*)d_in[6];   // [128,1024]
    const float* fcb  = (const float*)d_in[7];   // [128]
    float* out = (float*)d_out;                  // [64,128]

    cudaFuncSetAttribute(scan_kernel, cudaFuncAttributeMaxDynamicSharedMemorySize,
                         SCAN_SMEM_BYTES);

    void *pP = nullptr, *pS = nullptr;
    cudaGetSymbolAddress(&pP, g_P);
    cudaGetSymbolAddress(&pS, g_S);
    float* P  = (float*)pP;
    float* Sq = (float*)pS;

    proj_kernel<<<2048, 256>>>(x, wih0, bih, bhh, P, DIN);
    scan_kernel<<<GRID, 256, SCAN_SMEM_BYTES>>>(P, Sq, whh);
    proj_kernel<<<2048, 256>>>(Sq, wihr, bih + HDIM, bhh + HDIM, P, HDIM);
    scan_kernel<<<GRID, 256, SCAN_SMEM_BYTES>>>(P, Sq, whh + (size_t)HDIM * HDIM);
    proj_kernel<<<2048, 256>>>(Sq, wihr + (size_t)HDIM * HDIM, bih + 2 * HDIM, bhh + 2 * HDIM, P, HDIM);
    scan_kernel<<<GRID, 256, SCAN_SMEM_BYTES>>>(P, Sq, whh + 2 * (size_t)HDIM * HDIM);
    fc_kernel<<<BATCH, 128>>>(Sq, fcw, fcb, out);
}

// round 6
// speedup vs baseline: 1.3228x; 1.2056x over previous
#include <cuda_runtime.h>
#include <cstdint>
#include <cstddef>

#define BATCH 64
#define SEQT  512
#define DIN   256
#define HDIM  1024
#define DOUT  128
#define GRID  128

typedef unsigned long long u64;

// ---------------- scratch (device globals: allocation-free) ----------------
__device__ __align__(16) static float g_P[(size_t)BATCH * SEQT * HDIM]; // pre-activations
__device__ __align__(16) static float g_S[(size_t)BATCH * SEQT * HDIM]; // layer outputs / h
__device__ volatile unsigned g_flags[GRID];                             // barrier flags (zero-init)

// ---------------- packed f32x2 helpers ----------------
__device__ __forceinline__ void fma2(u64 &d, u64 a, u64 b) {
    asm("fma.rn.f32x2 %0, %1, %2, %0;" : "+l"(d) : "l"(a), "l"(b));
}
__device__ __forceinline__ u64 add2(u64 a, u64 b) {
    u64 r; asm("add.rn.f32x2 %0, %1, %2;" : "=l"(r) : "l"(a), "l"(b)); return r;
}
__device__ __forceinline__ float2 up2(u64 v) {
    float2 f; asm("mov.b64 {%0, %1}, %2;" : "=f"(f.x), "=f"(f.y) : "l"(v)); return f;
}

__device__ __forceinline__ uint32_t smem_u32(const void* p) {
    uint32_t a;
    asm("{ .reg .u64 t; cvta.to.shared.u64 t, %1; cvt.u32.u64 %0, t; }" : "=r"(a) : "l"(p));
    return a;
}
__device__ __forceinline__ void cpasync16(uint32_t dst, const void* src) {
    asm volatile("cp.async.cg.shared.global [%0], [%1], 16;" :: "r"(dst), "l"(src));
}
__device__ __forceinline__ void cpasync_commit_wait() {
    asm volatile("cp.async.commit_group;");
    asm volatile("cp.async.wait_group 0;" ::: "memory");
}

// ---------------- group barrier: 4 independent groups of 32 CTAs ----------------
__device__ __forceinline__ void gsync(unsigned gen, int gbase) {
    __syncthreads();
    if (threadIdx.x == 0) {
        __threadfence();                 // release prior global writes
        g_flags[blockIdx.x] = gen;       // volatile store
    }
    if (threadIdx.x < 32) {
        while (g_flags[gbase + threadIdx.x] < gen) { }
    }
    __syncthreads();
}

// ============================================================================
// Projection GEMM: C[32768][1024] = A[32768][K] @ W[1024][K]^T + (bi + bh)
// ============================================================================
__global__ void __launch_bounds__(256, 2) proj_kernel(
    const float* __restrict__ A, const float* __restrict__ W,
    const float* __restrict__ bi, const float* __restrict__ bh,
    float* __restrict__ C, int K)
{
    __shared__ __align__(16) float sA[16 * 132];
    __shared__ __align__(16) float sB[16 * 132];

    const int tid = threadIdx.x;
    const int tm = blockIdx.x >> 3;
    const int tn = blockIdx.x & 7;
    const int ty = tid >> 4;
    const int tx = tid & 15;
    const int lr = tid >> 2;
    const int lq = tid & 3;

    u64 acc[8][4];
    #pragma unroll
    for (int i = 0; i < 8; i++)
        #pragma unroll
        for (int j = 0; j < 4; j++) acc[i][j] = 0ull;

    const float* Ab = A + (size_t)(tm * 128) * K;
    const float* Wb = W + (size_t)(tn * 128) * K;

    for (int kc = 0; kc < K; kc += 16) {
        __syncthreads();
        #pragma unroll
        for (int p = 0; p < 2; p++) {
            const int rr = lr + p * 64;
            const float4 a4 = __ldg((const float4*)(Ab + (size_t)rr * K + kc + lq * 4));
            const float4 w4 = __ldg((const float4*)(Wb + (size_t)rr * K + kc + lq * 4));
            sA[(lq * 4 + 0) * 132 + rr] = a4.x;
            sA[(lq * 4 + 1) * 132 + rr] = a4.y;
            sA[(lq * 4 + 2) * 132 + rr] = a4.z;
            sA[(lq * 4 + 3) * 132 + rr] = a4.w;
            sB[(lq * 4 + 0) * 132 + rr] = w4.x;
            sB[(lq * 4 + 1) * 132 + rr] = w4.y;
            sB[(lq * 4 + 2) * 132 + rr] = w4.z;
            sB[(lq * 4 + 3) * 132 + rr] = w4.w;
        }
        __syncthreads();
        #pragma unroll
        for (int kk = 0; kk < 16; kk++) {
            const float4 a0 = *(const float4*)&sA[kk * 132 + ty * 4];
            const float4 a1 = *(const float4*)&sA[kk * 132 + 64 + ty * 4];
            const ulonglong2 bq0 = *(const ulonglong2*)&sB[kk * 132 + tx * 4];
            const ulonglong2 bq1 = *(const ulonglong2*)&sB[kk * 132 + 64 + tx * 4];
            const float am[8] = {a0.x, a0.y, a0.z, a0.w, a1.x, a1.y, a1.z, a1.w};
            #pragma unroll
            for (int i = 0; i < 8; i++) {
                u64 ad;
                asm("mov.b64 %0, {%1, %1};" : "=l"(ad) : "f"(am[i]));
                fma2(acc[i][0], ad, bq0.x);
                fma2(acc[i][1], ad, bq0.y);
                fma2(acc[i][2], ad, bq1.x);
                fma2(acc[i][3], ad, bq1.y);
            }
        }
    }

    const int n0 = tn * 128 + tx * 4;
    const int n1 = n0 + 64;
    float4 bia0, bia1;
    {
        const float4 i0 = __ldg((const float4*)(bi + n0));
        const float4 h0 = __ldg((const float4*)(bh + n0));
        const float4 i1 = __ldg((const float4*)(bi + n1));
        const float4 h1 = __ldg((const float4*)(bh + n1));
        bia0 = make_float4(i0.x + h0.x, i0.y + h0.y, i0.z + h0.z, i0.w + h0.w);
        bia1 = make_float4(i1.x + h1.x, i1.y + h1.y, i1.z + h1.z, i1.w + h1.w);
    }
    #pragma unroll
    for (int i = 0; i < 8; i++) {
        const int m = tm * 128 + (i < 4 ? ty * 4 + i : 64 + ty * 4 + (i - 4));
        const float2 c0 = up2(acc[i][0]), c1 = up2(acc[i][1]);
        const float2 c2 = up2(acc[i][2]), c3 = up2(acc[i][3]);
        *(float4*)(C + (size_t)m * HDIM + n0) =
            make_float4(c0.x + bia0.x, c0.y + bia0.y, c1.x + bia0.z, c1.y + bia0.w);
        *(float4*)(C + (size_t)m * HDIM + n1) =
            make_float4(c2.x + bia1.x, c2.y + bia1.y, c3.x + bia1.z, c3.y + bia1.w);
    }
}

// ============================================================================
// Recurrent scan with REGISTER-RESIDENT WEIGHTS.
// 128 CTAs x 256 thr, 1 CTA/SM, CTA tile [16b x 32o].
// Warp w owns k-range [128w, 128w+128); lane l owns output o0+l.
// Each lane holds Whh[o0+l][kw..kw+128) in 64 u64 regs for the whole layer.
// h_{t-1} staged to smem once per step; ALL lanes of a warp read the SAME
// h address -> pure broadcast, zero conflicts. k-packed f32x2 accumulation
// (acc[b] = (even,odd) partial sums), folded once at the end of each b.
// Reduce: 8 warp-partials in smem, one final pass. Group-local barrier.
// ============================================================================
#define SM_H   0                          // hS[16][1024]
#define SM_R   (16 * 1024)                // red: u64[8][512]
#define SCAN_SMEM_BYTES ((SM_R + 8 * 512 * 2) * 4)   // 98,304 B

__global__ void __launch_bounds__(256, 1) scan_kernel(
    const float* __restrict__ P, float* __restrict__ S,
    const float* __restrict__ Whh)
{
    extern __shared__ __align__(16) float sm[];
    float* hS = sm + SM_H;
    u64*   red = (u64*)(sm + SM_R);

    const int tid  = threadIdx.x;
    const int cta  = blockIdx.x;
    const int gbase = cta & ~31;        // barrier group base
    const int b0 = (cta >> 5) * 16;     // batch block
    const int o0 = (cta & 31) * 32;     // output block
    const int warp = tid >> 5;          // k-range owner: [warp*128, +128)
    const int lane = tid & 31;          // output owner: o0 + lane
    const int kb = warp * 128;

    // ---- load this lane's weight slice into registers (once per layer) ----
    u64 wreg[64];
    {
        const float* wrow = Whh + (size_t)(o0 + lane) * HDIM + kb;
        #pragma unroll
        for (int c = 0; c < 32; c++) {
            const float4 w4 = __ldg((const float4*)(wrow + c * 4));
            wreg[2 * c]     = ((const u64*)&w4)[0];
            wreg[2 * c + 1] = ((const u64*)&w4)[1];
        }
    }

    unsigned gen = g_flags[cta];        // persists across launches

    // Epilogue mapping: 2 adjacent outputs per thread
    const int pb = tid >> 4;
    const int po = (tid & 15) * 2;
    const size_t prow = ((size_t)(b0 + pb) * SEQT) * HDIM + o0 + po;

    // t = 0
    {
        const float2 p2 = *(const float2*)(P + prow);
        *(float2*)(S + prow) = make_float2(fmaxf(p2.x, 0.f), fmaxf(p2.y, 0.f));
    }
    gen++; gsync(gen, gbase);

    const uint32_t hS_a = smem_u32(hS);
    const float* Sb = S + (size_t)b0 * SEQT * HDIM;

    for (int t = 1; t < SEQT; t++) {
        const float2 p2 = __ldg((const float2*)(P + prow + (size_t)t * HDIM));

        // CTA-wide staging of h_{t-1}[b0..b0+16) (cp.async .cg = L2-coherent)
        {
            const size_t tprev = (size_t)(t - 1) * HDIM;
            #pragma unroll
            for (int p = 0; p < 16; p++) {
                const int i = p * 256 + tid;
                const int bb = i >> 8, qq = i & 255;
                cpasync16(hS_a + (uint32_t)(bb * 1024 + qq * 4) * 4,
                          Sb + (size_t)bb * SEQT * HDIM + tprev + qq * 4);
            }
            cpasync_commit_wait();
        }
        __syncthreads();

        // ---- compute: per lane, 16 batches x 1 output x 128 k ----
        u64 accF[16];
        #pragma unroll
        for (int b = 0; b < 16; b++) {
            const ulonglong2* hrow = (const ulonglong2*)&hS[b * 1024 + kb];
            u64 a0 = 0ull, a1 = 0ull;      // two interleaved chains
            #pragma unroll
            for (int c = 0; c < 32; c++) {
                const ulonglong2 hp = hrow[c];   // broadcast across warp
                fma2(a0, hp.x, wreg[2 * c]);
                fma2(a1, hp.y, wreg[2 * c + 1]);
            }
            accF[b] = add2(a0, a1);
        }

        // stash warp partials: red[warp][b][lane]
        #pragma unroll
        for (int b = 0; b < 16; b++)
            red[warp * 512 + b * 32 + lane] = accF[b];
        __syncthreads();

        // final reduce over 8 warps, fold (even,odd) k halves, relu, store
        {
            ulonglong2 v = *(const ulonglong2*)&red[pb * 32 + po];
            u64 s0 = v.x, s1 = v.y;
            #pragma unroll
            for (int w8 = 1; w8 < 8; w8++) {
                const ulonglong2 r = *(const ulonglong2*)&red[w8 * 512 + pb * 32 + po];
                s0 = add2(s0, r.x);
                s1 = add2(s1, r.y);
            }
            const float2 a0 = up2(s0), a1 = up2(s1);
            *(float2*)(S + prow + (size_t)t * HDIM) =
                make_float2(fmaxf(a0.x + a0.y + p2.x, 0.f),
                            fmaxf(a1.x + a1.y + p2.y, 0.f));
        }
        gen++; gsync(gen, gbase);
    }
}

// ============================================================================
// FC: out[64][128] = S[:, T-1, :] @ fc_w^T + fc_b
// ============================================================================
__global__ void __launch_bounds__(128) fc_kernel(
    const float* __restrict__ S, const float* __restrict__ fw,
    const float* __restrict__ fb, float* __restrict__ out)
{
    __shared__ __align__(16) float sx[HDIM];
    const int b = blockIdx.x, tid = threadIdx.x;
    const float* xrow = S + ((size_t)b * SEQT + (SEQT - 1)) * HDIM;
    for (int i = tid; i < HDIM / 4; i += 128)
        *(float4*)&sx[i * 4] = __ldcg((const float4*)(xrow + i * 4));
    __syncthreads();
    float acc = 0.f;
    const float* wrow = fw + (size_t)tid * HDIM;
    #pragma unroll 8
    for (int q = 0; q < HDIM / 4; q++) {
        const float4 w4 = __ldg((const float4*)(wrow + q * 4));
        const float4 x4 = *(const float4*)&sx[q * 4];
        acc += w4.x * x4.x + w4.y * x4.y + w4.z * x4.z + w4.w * x4.w;
    }
    out[(size_t)b * DOUT + tid] = acc + __ldg(fb + tid);
}

// ============================================================================
extern "C" void kernel_launch(void* const* d_in, const int* in_sizes, int n_in,
                              void* d_out, int out_size)
{
    const float* x    = (const float*)d_in[0];   // [64,512,256]
    const float* wih0 = (const float*)d_in[1];   // [1024,256]
    const float* wihr = (const float*)d_in[2];   // [2,1024,1024]
    const float* whh  = (const float*)d_in[3];   // [3,1024,1024]
    const float* bih  = (const float*)d_in[4];   // [3,1024]
    const float* bhh  = (const float*)d_in[5];   // [3,1024]
    const float* fcw  = (const float*)d_in[6];   // [128,1024]
    const float* fcb  = (const float*)d_in[7];   // [128]
    float* out = (float*)d_out;                  // [64,128]

    cudaFuncSetAttribute(scan_kernel, cudaFuncAttributeMaxDynamicSharedMemorySize,
                         SCAN_SMEM_BYTES);

    void *pP = nullptr, *pS = nullptr;
    cudaGetSymbolAddress(&pP, g_P);
    cudaGetSymbolAddress(&pS, g_S);
    float* P  = (float*)pP;
    float* Sq = (float*)pS;

    proj_kernel<<<2048, 256>>>(x, wih0, bih, bhh, P, DIN);
    scan_kernel<<<GRID, 256, SCAN_SMEM_BYTES>>>(P, Sq, whh);
    proj_kernel<<<2048, 256>>>(Sq, wihr, bih + HDIM, bhh + HDIM, P, HDIM);
    scan_kernel<<<GRID, 256, SCAN_SMEM_BYTES>>>(P, Sq, whh + (size_t)HDIM * HDIM);
    proj_kernel<<<2048, 256>>>(Sq, wihr + (size_t)HDIM * HDIM, bih + 2 * HDIM, bhh + 2 * HDIM, P, HDIM);
    scan_kernel<<<GRID, 256, SCAN_SMEM_BYTES>>>(P, Sq, whh + 2 * (size_t)HDIM * HDIM);
    fc_kernel<<<BATCH, 128>>>(Sq, fcw, fcb, out);
}